// round 6
// baseline (speedup 1.0000x reference)
#include <cuda_runtime.h>
#include <math.h>
#include <stdint.h>

// Problem shapes (fixed by the dataset).
#define MAX_N 4096
#define MAX_C 50257
#define EDIM  512

#define CSPLIT 9     // class split -> grid (64, 9) = 576 CTAs ~ 3.9/SM (good balance on 148 SMs)
#define TM 64        // rows per CTA
#define TN 128       // classes per tile
#define KT 64        // k-chunk
#define WP 68        // padded W-tile row stride in floats (272 B, 16B-aligned, 2-way max conflict)

// ---------------- device scratch (no allocations allowed) ----------------
__device__ float g_xn[MAX_N * EDIM];
__device__ float g_wn[MAX_C * EDIM];          // ~103 MB, zero-init BSS
__device__ int   g_label[MAX_N];
__device__ float g_tgt[MAX_N];
__device__ float g_partM[MAX_N * CSPLIT];
__device__ float g_partS[MAX_N * CSPLIT];
__device__ float g_rowloss[MAX_N];

// ---------------- cp.async helpers ----------------
__device__ __forceinline__ void cp_async16(uint32_t saddr, const void* gaddr, int pred16) {
    asm volatile("cp.async.cg.shared.global [%0], [%1], 16, %2;\n"
                 :: "r"(saddr), "l"(gaddr), "r"(pred16) : "memory");
}
__device__ __forceinline__ void cp_commit() {
    asm volatile("cp.async.commit_group;\n" ::: "memory");
}
__device__ __forceinline__ void cp_wait_all() {
    asm volatile("cp.async.wait_group 0;\n" ::: "memory");
}

// ---------------- row L2 normalization (x: which=0, W: which=1) ----------------
__global__ void k_norm_rows(const float* __restrict__ src, int E, int which) {
    float* dst = which ? g_wn : g_xn;
    int row = blockIdx.x;
    const float4* ip = reinterpret_cast<const float4*>(src) + (size_t)row * (E >> 2);
    float4*       op = reinterpret_cast<float4*>(dst)       + (size_t)row * (E >> 2);
    int nv = E >> 2;
    float ss = 0.f;
    for (int i = threadIdx.x; i < nv; i += blockDim.x) {
        float4 v = ip[i];
        ss += v.x * v.x + v.y * v.y + v.z * v.z + v.w * v.w;
    }
    __shared__ float red[4];
    #pragma unroll
    for (int m = 16; m; m >>= 1) ss += __shfl_xor_sync(0xffffffffu, ss, m);
    if ((threadIdx.x & 31) == 0) red[threadIdx.x >> 5] = ss;
    __syncthreads();
    float tot = red[0] + red[1] + red[2] + red[3];
    float scale = 1.f / fmaxf(sqrtf(tot), 1e-12f);
    for (int i = threadIdx.x; i < nv; i += blockDim.x) {
        float4 v = ip[i];
        v.x *= scale; v.y *= scale; v.z *= scale; v.w *= scale;
        op[i] = v;
    }
}

// ---------------- label dtype detection (int32 vs int64 storage) ----------------
__global__ void k_prep_labels(const int* __restrict__ li, int N) {
    int any = 0;
    for (int i = threadIdx.x; i < (N >> 1); i += blockDim.x)
        if (li[2 * i + 1] != 0) any = 1;
    int is32 = __syncthreads_or(any);
    if (is32) { for (int i = threadIdx.x; i < N; i += blockDim.x) g_label[i] = li[i]; }
    else      { for (int i = threadIdx.x; i < N; i += blockDim.x) g_label[i] = li[2 * i]; }
}

// ---------------- target cosine per row ----------------
__global__ void k_target_dot(int E) {
    int row = blockIdx.x;
    int lab = g_label[row];
    const float4* a = reinterpret_cast<const float4*>(g_xn) + (size_t)row * (E >> 2);
    const float4* b = reinterpret_cast<const float4*>(g_wn) + (size_t)lab * (E >> 2);
    float s = 0.f;
    for (int i = threadIdx.x; i < (E >> 2); i += blockDim.x) {
        float4 u = a[i], v = b[i];
        s += u.x * v.x + u.y * v.y + u.z * v.z + u.w * v.w;
    }
    __shared__ float red[4];
    #pragma unroll
    for (int m = 16; m; m >>= 1) s += __shfl_xor_sync(0xffffffffu, s, m);
    if ((threadIdx.x & 31) == 0) red[threadIdx.x >> 5] = s;
    __syncthreads();
    if (threadIdx.x == 0) g_tgt[row] = red[0] + red[1] + red[2] + red[3];
}

// ---------------- fused GEMM + online logsumexp ----------------
// Grid (N/TM, CSPLIT). Block 256 = 16 tx (class lanes) x 16 ty (4-row groups).
// Micro-tile 4 rows x 8 classes; W tiles double-buffered via cp.async.
__global__ void __launch_bounds__(256, 1) k_lse_gemm(int N, int E, int C) {
    extern __shared__ float sm[];
    float* xs = sm;                         // [TM][E]       fp32
    float* ws = sm + TM * E;                // [2][TN][WP]
    const int tid = threadIdx.x;
    const int tx = tid & 15;
    const int ty = tid >> 4;
    const int rb = blockIdx.x;
    const int sp = blockIdx.y;

    const int chunkC = (C + CSPLIT - 1) / CSPLIT;
    const int c0 = sp * chunkC;
    const int c1 = min(C, c0 + chunkC);

    uint32_t xs_s = (uint32_t)__cvta_generic_to_shared(xs);
    uint32_t ws_s = (uint32_t)__cvta_generic_to_shared(ws);

    // stage x tile (TM x E) via cp.async
    {
        const float4* xg = reinterpret_cast<const float4*>(g_xn) + (size_t)rb * TM * (E >> 2);
        int nx4 = TM * (E >> 2);            // 8192 vec4
        for (int i = tid; i < nx4; i += 256)
            cp_async16(xs_s + i * 16, xg + i, 16);
    }
    // stage first W chunk (c0, kb=0) into buffer 0
    {
        #pragma unroll
        for (int q = 0; q < 8; q++) {
            int v = tid + 256 * q;          // TN*(KT/4)=2048 vec4 slots
            int c = v >> 4;
            int kk = (v & 15) << 2;
            int cg = c0 + c;
            int ok = (cg < C);
            const float* gp = g_wn + (size_t)(ok ? cg : (C - 1)) * E + kk;
            cp_async16(ws_s + (c * WP + kk) * 4, gp, ok ? 16 : 0);
        }
    }
    cp_commit();
    cp_wait_all();
    __syncthreads();

    float runM[4], runS[4];
    #pragma unroll
    for (int i = 0; i < 4; i++) { runM[i] = -INFINITY; runS[i] = 0.f; }

    int buf = 0;
    for (int cb = c0; cb < c1; cb += TN) {
        float acc[4][8];
        #pragma unroll
        for (int i = 0; i < 4; i++)
            #pragma unroll
            for (int j = 0; j < 8; j++) acc[i][j] = 0.f;

        for (int kb = 0; kb < E; kb += KT) {
            // issue async load of the NEXT chunk into the other buffer
            int nkb = kb + KT, ncb = cb;
            if (nkb == E) { nkb = 0; ncb = cb + TN; }
            bool hn = (ncb < c1);
            if (hn) {
                uint32_t dst = ws_s + (buf ^ 1) * (TN * WP * 4);
                #pragma unroll
                for (int q = 0; q < 8; q++) {
                    int v = tid + 256 * q;
                    int c = v >> 4;
                    int kk = (v & 15) << 2;
                    int cg = ncb + c;
                    int ok = (cg < C);
                    const float* gp = g_wn + (size_t)(ok ? cg : (C - 1)) * E + nkb + kk;
                    cp_async16(dst + (c * WP + kk) * 4, gp, ok ? 16 : 0);
                }
                cp_commit();
            }

            const float* wsb = ws + buf * (TN * WP);
            #pragma unroll
            for (int k = 0; k < KT; k += 4) {
                float4 a[4], b[8];
                #pragma unroll
                for (int i = 0; i < 4; i++)
                    a[i] = *reinterpret_cast<const float4*>(&xs[(ty * 4 + i) * E + kb + k]);
                #pragma unroll
                for (int j = 0; j < 8; j++)
                    b[j] = *reinterpret_cast<const float4*>(&wsb[(tx + 16 * j) * WP + k]);
                #pragma unroll
                for (int i = 0; i < 4; i++)
                    #pragma unroll
                    for (int j = 0; j < 8; j++)
                        acc[i][j] += a[i].x * b[j].x + a[i].y * b[j].y
                                   + a[i].z * b[j].z + a[i].w * b[j].w;
            }

            cp_wait_all();
            __syncthreads();
            buf ^= 1;
        }

        // online logsumexp epilogue: butterfly over the 16 tx lanes per row
        #pragma unroll
        for (int i = 0; i < 4; i++) {
            float vv[8];
            float m = -INFINITY;
            #pragma unroll
            for (int j = 0; j < 8; j++) {
                vv[j] = (cb + tx + 16 * j < c1) ? acc[i][j] : -INFINITY;
                m = fmaxf(m, vv[j]);
            }
            #pragma unroll
            for (int d = 8; d; d >>= 1) m = fmaxf(m, __shfl_xor_sync(0xffffffffu, m, d));
            float nm = fmaxf(runM[i], m);
            float s = 0.f;
            #pragma unroll
            for (int j = 0; j < 8; j++) s += __expf(vv[j] - nm);
            #pragma unroll
            for (int d = 8; d; d >>= 1) s += __shfl_xor_sync(0xffffffffu, s, d);
            runS[i] = runS[i] * __expf(runM[i] - nm) + s;
            runM[i] = nm;
        }
    }

    if (tx == 0) {
        #pragma unroll
        for (int i = 0; i < 4; i++) {
            int row = rb * TM + ty * 4 + i;
            if (row < N) {
                g_partM[row * CSPLIT + sp] = runM[i];
                g_partS[row * CSPLIT + sp] = runS[i];
            }
        }
    }
}

// ---------------- combine splits + margin patch -> per-row loss ----------------
__global__ void k_combine(int N, float cosM, float sinM) {
    int row = blockIdx.x * blockDim.x + threadIdx.x;
    if (row >= N) return;
    float M = -INFINITY;
    #pragma unroll
    for (int s = 0; s < CSPLIT; s++) M = fmaxf(M, g_partM[row * CSPLIT + s]);
    float S = 0.f;
    #pragma unroll
    for (int s = 0; s < CSPLIT; s++)
        S += g_partS[row * CSPLIT + s] * __expf(g_partM[row * CSPLIT + s] - M);
    float t = g_tgt[row];
    t = fminf(1.f, fmaxf(-1.f, t));
    float st = sqrtf(fmaxf(0.f, 1.f - t * t));
    float cm = t * cosM - st * sinM;               // margin-adjusted target logit
    S += __expf(cm - M) - __expf(t - M);           // swap raw target term for cos_m term
    S = fmaxf(S, 1e-30f);
    float logz = M + __logf(S);
    g_rowloss[row] = logz - cm;
}

// ---------------- deterministic final mean ----------------
__global__ void k_reduce(float* __restrict__ out, int N) {
    __shared__ float red[8];
    float s = 0.f;
    for (int i = threadIdx.x; i < N; i += blockDim.x) s += g_rowloss[i];
    #pragma unroll
    for (int m = 16; m; m >>= 1) s += __shfl_xor_sync(0xffffffffu, s, m);
    if ((threadIdx.x & 31) == 0) red[threadIdx.x >> 5] = s;
    __syncthreads();
    if (threadIdx.x < 32) {
        float v = (threadIdx.x < (blockDim.x >> 5)) ? red[threadIdx.x] : 0.f;
        #pragma unroll
        for (int m = 16; m; m >>= 1) v += __shfl_xor_sync(0xffffffffu, v, m);
        if (threadIdx.x == 0) out[0] = v / (float)N;
    }
}

extern "C" void kernel_launch(void* const* d_in, const int* in_sizes, int n_in,
                              void* d_out, int out_size) {
    const float* x   = (const float*)d_in[0];
    const int*   lab = (const int*)d_in[1];
    const float* w   = (const float*)d_in[2];
    // Derive N and C from the float tensors only (label element-count dtype ambiguity avoided).
    int E = EDIM;
    int N = in_sizes[0] / E;
    int C = in_sizes[2] / E;

    size_t smem = (size_t)(TM * E + 2 * TN * WP) * sizeof(float);   // 200,704 B
    cudaFuncSetAttribute(k_lse_gemm, cudaFuncAttributeMaxDynamicSharedMemorySize, (int)smem);

    k_norm_rows<<<N, 128>>>(x, E, 0);
    k_norm_rows<<<C, 128>>>(w, E, 1);
    k_prep_labels<<<1, 256>>>(lab, N);
    k_target_dot<<<N, 128>>>(E);

    dim3 grid(N / TM, CSPLIT);
    k_lse_gemm<<<grid, 256, smem>>>(N, E, C);

    float cM = (float)cos(4.0);   // MARGIN = 4 rad
    float sM = (float)sin(4.0);
    k_combine<<<(N + 255) / 256, 256>>>(N, cM, sM);
    k_reduce<<<1, 256>>>((float*)d_out, N);
}

// round 8
// speedup vs baseline: 7.7356x; 7.7356x over previous
#include <cuda_runtime.h>
#include <cuda_bf16.h>
#include <math.h>
#include <stdint.h>

// Fixed dataset shapes
#define MAX_N 4096
#define MAX_C 50257
#define EDIM  512
#define NCB   197          // ceil(50257 / 256) class blocks

// ---------------- device scratch (no allocations allowed) ----------------
__device__ __nv_bfloat16 g_xb[MAX_N * EDIM];     // normalized x, bf16
__device__ __nv_bfloat16 g_wb[MAX_C * EDIM];     // normalized W, bf16 (~51.5 MB)
__device__ int   g_label[MAX_N];
__device__ float g_tgt[MAX_N];
__device__ float g_partS[(size_t)MAX_N * NCB];   // per (row, classblock) sum of exp(cos-1)
__device__ float g_rowloss[MAX_N];

// ---------------- PTX helpers (all plain sm_80+ features; no 103a gating) ----------------
__device__ __forceinline__ uint32_t smem_u32(const void* p) {
    return (uint32_t)__cvta_generic_to_shared(p);
}
__device__ __forceinline__ void cp_async16(uint32_t saddr, const void* gaddr, int srcsz) {
    asm volatile("cp.async.cg.shared.global [%0], [%1], 16, %2;\n"
                 :: "r"(saddr), "l"(gaddr), "r"(srcsz) : "memory");
}
__device__ __forceinline__ void cp_commit() { asm volatile("cp.async.commit_group;\n" ::: "memory"); }
template <int n>
__device__ __forceinline__ void cp_wait_group() {
    asm volatile("cp.async.wait_group %0;\n" :: "n"(n) : "memory");
}
__device__ __forceinline__ void ldsm_x4(uint32_t& r0, uint32_t& r1, uint32_t& r2, uint32_t& r3,
                                        uint32_t addr) {
    asm volatile("ldmatrix.sync.aligned.m8n8.x4.shared.b16 {%0,%1,%2,%3}, [%4];"
                 : "=r"(r0), "=r"(r1), "=r"(r2), "=r"(r3) : "r"(addr));
}
__device__ __forceinline__ void mma16816(float* c, uint32_t a0, uint32_t a1, uint32_t a2,
                                         uint32_t a3, uint32_t b0, uint32_t b1) {
    asm volatile("mma.sync.aligned.m16n8k16.row.col.f32.bf16.bf16.f32 "
                 "{%0,%1,%2,%3}, {%4,%5,%6,%7}, {%8,%9}, {%0,%1,%2,%3};"
                 : "+f"(c[0]), "+f"(c[1]), "+f"(c[2]), "+f"(c[3])
                 : "r"(a0), "r"(a1), "r"(a2), "r"(a3), "r"(b0), "r"(b1));
}
__device__ __forceinline__ uint32_t sw128(uint32_t b) { return b ^ ((b >> 3) & 0x70); }

// exp(v-1) for v in [-1, 1+eps]: degree-8 Taylor (exact coeffs e^-1/k!), max err ~1.1e-6
__device__ __forceinline__ float expv(float v) {
    float p = 9.123994e-6f;
    p = fmaf(p, v, 7.2991953e-5f);
    p = fmaf(p, v, 5.10943668e-4f);
    p = fmaf(p, v, 3.06566201e-3f);
    p = fmaf(p, v, 1.5328310049e-2f);
    p = fmaf(p, v, 6.1313240195e-2f);
    p = fmaf(p, v, 1.83939720586e-1f);
    p = fmaf(p, v, 3.67879441171e-1f);
    p = fmaf(p, v, 3.67879441171e-1f);
    return p;
}

// ---------------- normalization: fp32 src -> bf16 normalized rows ----------------
__global__ void k_norm_rows(const float* __restrict__ src, int which) {
    __nv_bfloat16* dst = which ? g_wb : g_xb;
    int row = blockIdx.x;
    const float4* ip = reinterpret_cast<const float4*>(src) + (size_t)row * (EDIM >> 2);
    float ss = 0.f;
    for (int i = threadIdx.x; i < (EDIM >> 2); i += blockDim.x) {
        float4 v = ip[i];
        ss += v.x * v.x + v.y * v.y + v.z * v.z + v.w * v.w;
    }
    __shared__ float red[4];
    #pragma unroll
    for (int m = 16; m; m >>= 1) ss += __shfl_xor_sync(0xffffffffu, ss, m);
    if ((threadIdx.x & 31) == 0) red[threadIdx.x >> 5] = ss;
    __syncthreads();
    float tot = red[0] + red[1] + red[2] + red[3];
    float scale = 1.f / fmaxf(sqrtf(tot), 1e-12f);
    __nv_bfloat162* op = reinterpret_cast<__nv_bfloat162*>(dst) + (size_t)row * (EDIM >> 1);
    for (int i = threadIdx.x; i < (EDIM >> 2); i += blockDim.x) {
        float4 v = ip[i];
        op[2 * i]     = __floats2bfloat162_rn(v.x * scale, v.y * scale);
        op[2 * i + 1] = __floats2bfloat162_rn(v.z * scale, v.w * scale);
    }
}

// ---------------- label dtype detection (int32 vs int64 storage) ----------------
__global__ void k_prep_labels(const int* __restrict__ li, int N) {
    int any = 0;
    for (int i = threadIdx.x; i < (N >> 1); i += blockDim.x)
        if (li[2 * i + 1] != 0) any = 1;
    int is32 = __syncthreads_or(any);
    if (is32) { for (int i = threadIdx.x; i < N; i += blockDim.x) g_label[i] = li[i]; }
    else      { for (int i = threadIdx.x; i < N; i += blockDim.x) g_label[i] = li[2 * i]; }
}

// ---------------- target cosine per row (bf16 inputs, fp32 accumulate) ----------------
__global__ void k_target_dot() {
    int row = blockIdx.x;
    int lab = g_label[row];
    const __nv_bfloat162* a = reinterpret_cast<const __nv_bfloat162*>(g_xb) + (size_t)row * (EDIM >> 1);
    const __nv_bfloat162* b = reinterpret_cast<const __nv_bfloat162*>(g_wb) + (size_t)lab * (EDIM >> 1);
    float s = 0.f;
    for (int i = threadIdx.x; i < (EDIM >> 1); i += blockDim.x) {
        float2 u = __bfloat1622float2(a[i]);
        float2 v = __bfloat1622float2(b[i]);
        s += u.x * v.x + u.y * v.y;
    }
    __shared__ float red[4];
    #pragma unroll
    for (int m = 16; m; m >>= 1) s += __shfl_xor_sync(0xffffffffu, s, m);
    if ((threadIdx.x & 31) == 0) red[threadIdx.x >> 5] = s;
    __syncthreads();
    if (threadIdx.x == 0) g_tgt[row] = red[0] + red[1] + red[2] + red[3];
}

// ---------------- HMMA GEMM + fused sum-exp ----------------
// Grid (N/128, NCB). Block 256 = 8 warps in 2(m) x 4(n); each warp owns a 64x64 subtile.
// SMEM: A[2][128][128B] @0 (32KB), B[2][256][128B] @32768 (64KB), srow[4][128] @98304 (2KB).
#define SM_B0   32768
#define SM_SROW 98304
#define SM_TOT  100352

__device__ __forceinline__ void load_tiles(uint32_t sb, int stage, int rb, int cb, int kb,
                                           int C, int tid) {
    uint32_t abase = sb + stage * 16384;
    const __nv_bfloat16* ag = g_xb + ((size_t)rb * 128) * EDIM + kb * 64;
    #pragma unroll
    for (int q = 0; q < 4; q++) {               // 1024 16B chunks for A
        int i = tid + q * 256;
        int row = i >> 3, s16 = i & 7;
        cp_async16(abase + sw128(row * 128 + s16 * 16), ag + (size_t)row * EDIM + s16 * 8, 16);
    }
    uint32_t bbase = sb + SM_B0 + stage * 32768;
    #pragma unroll
    for (int q = 0; q < 8; q++) {               // 2048 16B chunks for B
        int i = tid + q * 256;
        int row = i >> 3, s16 = i & 7;
        int cls = cb * 256 + row;
        int ok = (cls < C);
        cp_async16(bbase + sw128(row * 128 + s16 * 16),
                   g_wb + (size_t)(ok ? cls : 0) * EDIM + kb * 64 + s16 * 8, ok ? 16 : 0);
    }
}

__global__ void __launch_bounds__(256, 1) k_lse_mma(int N, int C) {
    extern __shared__ __align__(128) char smem[];
    const uint32_t sb = smem_u32(smem);
    const int tid  = threadIdx.x;
    const int warp = tid >> 5;
    const int lane = tid & 31;
    const int warp_m = warp >> 2;       // 0..1
    const int warp_n = warp & 3;        // 0..3
    const int rb = blockIdx.x;
    const int cb = blockIdx.y;

    float acc[4][8][4];
    #pragma unroll
    for (int mf = 0; mf < 4; mf++)
        #pragma unroll
        for (int nf = 0; nf < 8; nf++)
            #pragma unroll
            for (int j = 0; j < 4; j++) acc[mf][nf][j] = 0.f;

    // ldmatrix lane geometry (row within 16-row group, 16B k-offset within k16 block)
    const int lrow = (lane & 7) + ((lane >> 3) & 1) * 8;
    const int lkb  = ((lane >> 4) & 1) * 16;

    load_tiles(sb, 0, rb, cb, 0, C, tid);
    cp_commit();

    int buf = 0;
    for (int kb = 0; kb < 8; kb++) {
        if (kb < 7) {
            load_tiles(sb, buf ^ 1, rb, cb, kb + 1, C, tid);
            cp_commit();
            cp_wait_group<1>();
        } else {
            cp_wait_group<0>();
        }
        __syncthreads();

        uint32_t abase = sb + buf * 16384;
        uint32_t bbase = sb + SM_B0 + buf * 32768;
        const int arow = warp_m * 64 + lrow;
        const int brow = warp_n * 64 + lrow;

        #pragma unroll
        for (int kf = 0; kf < 4; kf++) {
            uint32_t a[4][4];
            #pragma unroll
            for (int mf = 0; mf < 4; mf++)
                ldsm_x4(a[mf][0], a[mf][1], a[mf][2], a[mf][3],
                        abase + sw128((arow + mf * 16) * 128 + kf * 32 + lkb));
            uint32_t b[8][2];
            #pragma unroll
            for (int np = 0; np < 4; np++) {
                uint32_t r0, r1, r2, r3;
                ldsm_x4(r0, r1, r2, r3,
                        bbase + sw128((brow + np * 16) * 128 + kf * 32 + lkb));
                b[np * 2][0] = r0; b[np * 2 + 1][0] = r1;
                b[np * 2][1] = r2; b[np * 2 + 1][1] = r3;
            }
            #pragma unroll
            for (int mf = 0; mf < 4; mf++)
                #pragma unroll
                for (int nf = 0; nf < 8; nf++)
                    mma16816(acc[mf][nf], a[mf][0], a[mf][1], a[mf][2], a[mf][3],
                             b[nf][0], b[nf][1]);
        }
        __syncthreads();
        buf ^= 1;
    }

    // ---- epilogue: sum exp(v-1) per row over this CTA's 256 classes ----
    float rs[8];
    #pragma unroll
    for (int i = 0; i < 8; i++) rs[i] = 0.f;
    const bool full = (cb * 256 + 256) <= C;
    const int colb = cb * 256 + warp_n * 64 + (lane & 3) * 2;
    #pragma unroll
    for (int mf = 0; mf < 4; mf++) {
        #pragma unroll
        for (int nf = 0; nf < 8; nf++) {
            float* c = acc[mf][nf];
            if (full) {
                rs[mf * 2]     += expv(c[0]) + expv(c[1]);
                rs[mf * 2 + 1] += expv(c[2]) + expv(c[3]);
            } else {
                int c0 = colb + nf * 8;
                if (c0 < C)     { rs[mf * 2] += expv(c[0]); rs[mf * 2 + 1] += expv(c[2]); }
                if (c0 + 1 < C) { rs[mf * 2] += expv(c[1]); rs[mf * 2 + 1] += expv(c[3]); }
            }
        }
    }
    #pragma unroll
    for (int i = 0; i < 8; i++) {
        rs[i] += __shfl_xor_sync(0xffffffffu, rs[i], 1);
        rs[i] += __shfl_xor_sync(0xffffffffu, rs[i], 2);
    }
    float* srow = reinterpret_cast<float*>(smem + SM_SROW);
    if ((lane & 3) == 0) {
        #pragma unroll
        for (int mf = 0; mf < 4; mf++) {
            int r = warp_m * 64 + mf * 16 + (lane >> 2);
            srow[warp_n * 128 + r]     = rs[mf * 2];
            srow[warp_n * 128 + r + 8] = rs[mf * 2 + 1];
        }
    }
    __syncthreads();
    if (tid < 128) {
        float s = srow[tid] + srow[128 + tid] + srow[256 + tid] + srow[384 + tid];
        g_partS[(size_t)(rb * 128 + tid) * NCB + cb] = s;
    }
}

// ---------------- combine classblocks + margin patch (fixed ref max = 1) ----------------
__global__ void k_combine(int N, float cosM, float sinM) {
    int row = blockIdx.x * blockDim.x + threadIdx.x;
    if (row >= N) return;
    float S = 0.f;
    const float* p = g_partS + (size_t)row * NCB;
    for (int s = 0; s < NCB; s++) S += p[s];
    float t = g_tgt[row];
    t = fminf(1.f, fmaxf(-1.f, t));
    float st = sqrtf(fmaxf(0.f, 1.f - t * t));
    float cm = t * cosM - st * sinM;
    S += expf(cm - 1.f) - expf(t - 1.f);     // swap raw target term for margin term
    S = fmaxf(S, 1e-30f);
    g_rowloss[row] = (1.f + logf(S)) - cm;
}

__global__ void k_reduce(float* __restrict__ out, int N) {
    __shared__ float red[8];
    float s = 0.f;
    for (int i = threadIdx.x; i < N; i += blockDim.x) s += g_rowloss[i];
    #pragma unroll
    for (int m = 16; m; m >>= 1) s += __shfl_xor_sync(0xffffffffu, s, m);
    if ((threadIdx.x & 31) == 0) red[threadIdx.x >> 5] = s;
    __syncthreads();
    if (threadIdx.x < 32) {
        float v = (threadIdx.x < (blockDim.x >> 5)) ? red[threadIdx.x] : 0.f;
        #pragma unroll
        for (int m = 16; m; m >>= 1) v += __shfl_xor_sync(0xffffffffu, v, m);
        if (threadIdx.x == 0) out[0] = v / (float)N;
    }
}

extern "C" void kernel_launch(void* const* d_in, const int* in_sizes, int n_in,
                              void* d_out, int out_size) {
    const float* x   = (const float*)d_in[0];
    const int*   lab = (const int*)d_in[1];
    const float* w   = (const float*)d_in[2];
    int N = in_sizes[0] / EDIM;
    int C = in_sizes[2] / EDIM;

    cudaFuncSetAttribute(k_lse_mma, cudaFuncAttributeMaxDynamicSharedMemorySize, SM_TOT);

    k_norm_rows<<<N, 128>>>(x, 0);
    k_norm_rows<<<C, 128>>>(w, 1);
    k_prep_labels<<<1, 256>>>(lab, N);
    k_target_dot<<<N, 128>>>();

    dim3 grid(N / 128, NCB);
    k_lse_mma<<<grid, 256, SM_TOT>>>(N, C);

    float cM = (float)cos(4.0);   // MARGIN = 4 rad
    float sM = (float)sin(4.0);
    k_combine<<<(N + 255) / 256, 256>>>(N, cM, sM);
    k_reduce<<<1, 256>>>((float*)d_out, N);
}

// round 9
// speedup vs baseline: 8.6504x; 1.1183x over previous
#include <cuda_runtime.h>
#include <cuda_bf16.h>
#include <math.h>
#include <stdint.h>

// Fixed dataset shapes
#define MAX_N 4096
#define MAX_C 50257
#define EDIM  512
#define NCB   197          // ceil(50257 / 256) class blocks

// ---------------- device scratch (no allocations allowed) ----------------
__device__ __nv_bfloat16 g_xb[MAX_N * EDIM];     // normalized x, bf16
__device__ __nv_bfloat16 g_wb[MAX_C * EDIM];     // normalized W, bf16 (~51.5 MB)
__device__ int   g_label[MAX_N];
__device__ float g_tgt[MAX_N];
__device__ float g_partS[(size_t)NCB * MAX_N];   // [cb][row] sum of exp(cos-1)
__device__ float g_rowloss[MAX_N];

// ---------------- PTX helpers (sm_80-class + base-sm_100 f32x2; no 'a' gating) --------
__device__ __forceinline__ uint32_t smem_u32(const void* p) {
    return (uint32_t)__cvta_generic_to_shared(p);
}
__device__ __forceinline__ void cp_async16(uint32_t saddr, const void* gaddr, int srcsz) {
    asm volatile("cp.async.cg.shared.global [%0], [%1], 16, %2;\n"
                 :: "r"(saddr), "l"(gaddr), "r"(srcsz) : "memory");
}
__device__ __forceinline__ void cp_commit() { asm volatile("cp.async.commit_group;\n" ::: "memory"); }
template <int n>
__device__ __forceinline__ void cp_wait_group() {
    asm volatile("cp.async.wait_group %0;\n" :: "n"(n) : "memory");
}
__device__ __forceinline__ void ldsm_x4(uint32_t& r0, uint32_t& r1, uint32_t& r2, uint32_t& r3,
                                        uint32_t addr) {
    asm volatile("ldmatrix.sync.aligned.m8n8.x4.shared.b16 {%0,%1,%2,%3}, [%4];"
                 : "=r"(r0), "=r"(r1), "=r"(r2), "=r"(r3) : "r"(addr));
}
__device__ __forceinline__ void mma16816(float* c, uint32_t a0, uint32_t a1, uint32_t a2,
                                         uint32_t a3, uint32_t b0, uint32_t b1) {
    asm volatile("mma.sync.aligned.m16n8k16.row.col.f32.bf16.bf16.f32 "
                 "{%0,%1,%2,%3}, {%4,%5,%6,%7}, {%8,%9}, {%0,%1,%2,%3};"
                 : "+f"(c[0]), "+f"(c[1]), "+f"(c[2]), "+f"(c[3])
                 : "r"(a0), "r"(a1), "r"(a2), "r"(a3), "r"(b0), "r"(b1));
}
__device__ __forceinline__ uint32_t sw128(uint32_t b) { return b ^ ((b >> 3) & 0x70); }

// packed f32x2 (PTX ISA 8.6, sm_100+ base feature)
__device__ __forceinline__ uint64_t f2pack(float x, float y) {
    uint64_t r;
    asm("mov.b64 %0, {%1, %2};" : "=l"(r) : "r"(__float_as_uint(x)), "r"(__float_as_uint(y)));
    return r;
}
__device__ __forceinline__ float f2sum(uint64_t v) {
    uint32_t a, b;
    asm("mov.b64 {%0, %1}, %2;" : "=r"(a), "=r"(b) : "l"(v));
    return __uint_as_float(a) + __uint_as_float(b);
}
__device__ __forceinline__ uint64_t fma2(uint64_t a, uint64_t b, uint64_t c) {
    uint64_t d;
    asm("fma.rn.f32x2 %0, %1, %2, %3;" : "=l"(d) : "l"(a), "l"(b), "l"(c));
    return d;
}
__device__ __forceinline__ uint64_t add2(uint64_t a, uint64_t b) {
    uint64_t d;
    asm("add.rn.f32x2 %0, %1, %2;" : "=l"(d) : "l"(a), "l"(b));
    return d;
}

// exp(v-1), deg-8 Taylor (coeffs e^-1/k!), |v|<=1: max err ~1.1e-6 (data has |v|<~0.35)
#define EC0 3.67879441171e-1f
#define EC1 3.67879441171e-1f
#define EC2 1.83939720586e-1f
#define EC3 6.1313240195e-2f
#define EC4 1.5328310049e-2f
#define EC5 3.06566201e-3f
#define EC6 5.10943668e-4f
#define EC7 7.2991953e-5f
#define EC8 9.123994e-6f
__device__ __forceinline__ float expv(float v) {
    float p = EC8;
    p = fmaf(p, v, EC7); p = fmaf(p, v, EC6); p = fmaf(p, v, EC5);
    p = fmaf(p, v, EC4); p = fmaf(p, v, EC3); p = fmaf(p, v, EC2);
    p = fmaf(p, v, EC1); p = fmaf(p, v, EC0);
    return p;
}

// ---------------- normalization: fp32 src -> bf16 normalized rows (warp per row) ------
__global__ void k_norm_rows(const float* __restrict__ src, int nrows, int which) {
    __nv_bfloat16* dst = which ? g_wb : g_xb;
    int row = blockIdx.x * 4 + (threadIdx.x >> 5);
    if (row >= nrows) return;
    int lane = threadIdx.x & 31;
    const float4* ip = reinterpret_cast<const float4*>(src) + (size_t)row * (EDIM >> 2);
    float4 v[4];
    float ss = 0.f;
    #pragma unroll
    for (int q = 0; q < 4; q++) {
        v[q] = ip[lane + 32 * q];
        ss += v[q].x * v[q].x + v[q].y * v[q].y + v[q].z * v[q].z + v[q].w * v[q].w;
    }
    #pragma unroll
    for (int m = 16; m; m >>= 1) ss += __shfl_xor_sync(0xffffffffu, ss, m);
    float scale = 1.f / fmaxf(sqrtf(ss), 1e-12f);
    __nv_bfloat162* op = reinterpret_cast<__nv_bfloat162*>(dst) + (size_t)row * (EDIM >> 1);
    #pragma unroll
    for (int q = 0; q < 4; q++) {
        int i = lane + 32 * q;
        op[2 * i]     = __floats2bfloat162_rn(v[q].x * scale, v[q].y * scale);
        op[2 * i + 1] = __floats2bfloat162_rn(v[q].z * scale, v[q].w * scale);
    }
}

// ---------------- label dtype detection (int32 vs int64 storage) ----------------
__global__ void k_prep_labels(const int* __restrict__ li, int N) {
    int any = 0;
    for (int i = threadIdx.x; i < (N >> 1); i += blockDim.x)
        if (li[2 * i + 1] != 0) any = 1;
    int is32 = __syncthreads_or(any);
    if (is32) { for (int i = threadIdx.x; i < N; i += blockDim.x) g_label[i] = li[i]; }
    else      { for (int i = threadIdx.x; i < N; i += blockDim.x) g_label[i] = li[2 * i]; }
}

// ---------------- target cosine per row (bf16 inputs, fp32 accumulate) ----------------
__global__ void k_target_dot() {
    int row = blockIdx.x;
    int lab = g_label[row];
    const __nv_bfloat162* a = reinterpret_cast<const __nv_bfloat162*>(g_xb) + (size_t)row * (EDIM >> 1);
    const __nv_bfloat162* b = reinterpret_cast<const __nv_bfloat162*>(g_wb) + (size_t)lab * (EDIM >> 1);
    float s = 0.f;
    for (int i = threadIdx.x; i < (EDIM >> 1); i += blockDim.x) {
        float2 u = __bfloat1622float2(a[i]);
        float2 v = __bfloat1622float2(b[i]);
        s += u.x * v.x + u.y * v.y;
    }
    __shared__ float red[4];
    #pragma unroll
    for (int m = 16; m; m >>= 1) s += __shfl_xor_sync(0xffffffffu, s, m);
    if ((threadIdx.x & 31) == 0) red[threadIdx.x >> 5] = s;
    __syncthreads();
    if (threadIdx.x == 0) g_tgt[row] = red[0] + red[1] + red[2] + red[3];
}

// ---------------- persistent HMMA GEMM + fused sum-exp ----------------
// Grid 148 (1 CTA/SM). Block 256 = 8 warps (2m x 4n), warp subtile 64x64.
// SMEM: A resident [8 chunks][128 rows][128B] = 128KB @0,
//       B ring 3 stages x [256 rows][128B] = 96KB @131072, srow 2KB @229376.
#define SM_B    131072
#define SM_SROW 229376
#define SM_TOT  231424
#define NPERS   148

__device__ __forceinline__ void load_A(uint32_t sb, int rb, int tid) {
    const __nv_bfloat16* ag = g_xb + ((size_t)rb * 128) * EDIM;
    for (int q = 0; q < 32; q++) {            // 8192 16B chunks
        int i = tid + q * 256;
        int kc = i >> 10, j = i & 1023;
        int row = j >> 3, s16 = j & 7;
        cp_async16(sb + kc * 16384 + sw128(row * 128 + s16 * 16),
                   ag + (size_t)row * EDIM + kc * 64 + s16 * 8, 16);
    }
}
__device__ __forceinline__ void load_B(uint32_t sb, int stage, int cb, int kb, int C, int tid) {
    uint32_t bbase = sb + SM_B + stage * 32768;
    #pragma unroll
    for (int q = 0; q < 8; q++) {             // 2048 16B chunks
        int i = tid + q * 256;
        int row = i >> 3, s16 = i & 7;
        int cls = cb * 256 + row;
        int ok = (cls < C);
        cp_async16(bbase + sw128(row * 128 + s16 * 16),
                   g_wb + (size_t)(ok ? cls : 0) * EDIM + kb * 64 + s16 * 8, ok ? 16 : 0);
    }
}

__global__ void __launch_bounds__(256, 1) k_lse_mma(int N, int C) {
    extern __shared__ __align__(128) char smem[];
    const uint32_t sb = smem_u32(smem);
    const int tid  = threadIdx.x;
    const int warp = tid >> 5;
    const int lane = tid & 31;
    const int warp_m = warp >> 2;       // 0..1
    const int warp_n = warp & 3;        // 0..3

    const int nrb = N >> 7;
    const int ncb = (C + 255) >> 8;
    const int tot = nrb * ncb;
    int ts = (int)(((long long)blockIdx.x * tot) / NPERS);
    int te = (int)(((long long)(blockIdx.x + 1) * tot) / NPERS);

    // ldmatrix lane geometry
    const int lrow = (lane & 7) + ((lane >> 3) & 1) * 8;
    const int lkb  = ((lane >> 4) & 1) * 16;
    const int arow = warp_m * 64 + lrow;
    const int brow = warp_n * 64 + lrow;
    float* srow = reinterpret_cast<float*>(smem + SM_SROW);

    float acc[4][8][4];

    int t = ts;
    while (t < te) {
        int rb = t / ncb;
        int segEnd = min(te, (rb + 1) * ncb);
        int L = (segEnd - t) * 8;

        load_A(sb, rb, tid); cp_commit();
        load_B(sb, 0, (t) % ncb, 0, C, tid); cp_commit();
        load_B(sb, 1, (t + (1 >> 3)) % ncb, 1, C, tid); cp_commit();

        for (int j = 0; j < L; j++) {
            int kb = j & 7;
            cp_wait_group<1>(); __syncthreads();
            // prefetch j+2 AFTER the barrier (stage (j+2)%3 was consumed at iter j-1)
            if (j + 2 < L) {
                int nj = j + 2;
                load_B(sb, nj % 3, (t + (nj >> 3)) % ncb, nj & 7, C, tid);
            }
            cp_commit();

            if (kb == 0) {
                #pragma unroll
                for (int mf = 0; mf < 4; mf++)
                    #pragma unroll
                    for (int nf = 0; nf < 8; nf++)
                        #pragma unroll
                        for (int q = 0; q < 4; q++) acc[mf][nf][q] = 0.f;
            }

            uint32_t abase = sb + kb * 16384;
            uint32_t bbase = sb + SM_B + (j % 3) * 32768;
            #pragma unroll
            for (int kf = 0; kf < 4; kf++) {
                uint32_t a[4][4];
                #pragma unroll
                for (int mf = 0; mf < 4; mf++)
                    ldsm_x4(a[mf][0], a[mf][1], a[mf][2], a[mf][3],
                            abase + sw128((arow + mf * 16) * 128 + kf * 32 + lkb));
                uint32_t b[8][2];
                #pragma unroll
                for (int np = 0; np < 4; np++) {
                    uint32_t r0, r1, r2, r3;
                    ldsm_x4(r0, r1, r2, r3,
                            bbase + sw128((brow + np * 16) * 128 + kf * 32 + lkb));
                    b[np * 2][0] = r0; b[np * 2 + 1][0] = r1;
                    b[np * 2][1] = r2; b[np * 2 + 1][1] = r3;
                }
                #pragma unroll
                for (int mf = 0; mf < 4; mf++)
                    #pragma unroll
                    for (int nf = 0; nf < 8; nf++)
                        mma16816(acc[mf][nf], a[mf][0], a[mf][1], a[mf][2], a[mf][3],
                                 b[nf][0], b[nf][1]);
            }

            if (kb == 7) {
                // ---- epilogue for tile (rb, cb): sum exp(v-1) per row ----
                int ct = t + (j >> 3);
                int cb = ct % ncb;
                float rs[8];
                const bool full = (cb * 256 + 256) <= C;
                if (full) {
                    uint64_t c8 = f2pack(EC8, EC8), c7 = f2pack(EC7, EC7),
                             c6 = f2pack(EC6, EC6), c5 = f2pack(EC5, EC5),
                             c4 = f2pack(EC4, EC4), c3 = f2pack(EC3, EC3),
                             c2 = f2pack(EC2, EC2), c1 = f2pack(EC1, EC1),
                             c0 = f2pack(EC0, EC0);
                    uint64_t rp[8];
                    #pragma unroll
                    for (int i = 0; i < 8; i++) rp[i] = 0;   // (0.0f,0.0f)
                    #pragma unroll
                    for (int mf = 0; mf < 4; mf++) {
                        #pragma unroll
                        for (int nf = 0; nf < 8; nf++) {
                            float* c = acc[mf][nf];
                            #pragma unroll
                            for (int h = 0; h < 2; h++) {
                                uint64_t v = f2pack(c[2 * h], c[2 * h + 1]);
                                uint64_t p = c8;
                                p = fma2(p, v, c7); p = fma2(p, v, c6); p = fma2(p, v, c5);
                                p = fma2(p, v, c4); p = fma2(p, v, c3); p = fma2(p, v, c2);
                                p = fma2(p, v, c1); p = fma2(p, v, c0);
                                rp[mf * 2 + h] = add2(rp[mf * 2 + h], p);
                            }
                        }
                    }
                    #pragma unroll
                    for (int i = 0; i < 8; i++) rs[i] = f2sum(rp[i]);
                } else {
                    #pragma unroll
                    for (int i = 0; i < 8; i++) rs[i] = 0.f;
                    const int colb = cb * 256 + warp_n * 64 + (lane & 3) * 2;
                    #pragma unroll
                    for (int mf = 0; mf < 4; mf++)
                        #pragma unroll
                        for (int nf = 0; nf < 8; nf++) {
                            float* c = acc[mf][nf];
                            int cc = colb + nf * 8;
                            if (cc < C)     { rs[mf * 2] += expv(c[0]); rs[mf * 2 + 1] += expv(c[2]); }
                            if (cc + 1 < C) { rs[mf * 2] += expv(c[1]); rs[mf * 2 + 1] += expv(c[3]); }
                        }
                }
                #pragma unroll
                for (int i = 0; i < 8; i++) {
                    rs[i] += __shfl_xor_sync(0xffffffffu, rs[i], 1);
                    rs[i] += __shfl_xor_sync(0xffffffffu, rs[i], 2);
                }
                if ((lane & 3) == 0) {
                    #pragma unroll
                    for (int mf = 0; mf < 4; mf++) {
                        int r = warp_m * 64 + mf * 16 + (lane >> 2);
                        srow[warp_n * 128 + r]     = rs[mf * 2];
                        srow[warp_n * 128 + r + 8] = rs[mf * 2 + 1];
                    }
                }
                __syncthreads();
                if (tid < 128) {
                    float s = srow[tid] + srow[128 + tid] + srow[256 + tid] + srow[384 + tid];
                    g_partS[(size_t)cb * MAX_N + rb * 128 + tid] = s;
                }
                __syncthreads();
            }
        }
        cp_wait_group<0>(); __syncthreads();   // drain before A reload / exit
        t = segEnd;
    }
}

// ---------------- combine classblocks + margin patch (fixed ref max = 1) --------------
__global__ void k_combine(int N, int ncb, float cosM, float sinM) {
    int row = blockIdx.x * blockDim.x + threadIdx.x;
    if (row >= N) return;
    float S = 0.f;
    const float* p = g_partS + row;
    for (int s = 0; s < ncb; s++) S += p[(size_t)s * MAX_N];
    float t = g_tgt[row];
    t = fminf(1.f, fmaxf(-1.f, t));
    float st = sqrtf(fmaxf(0.f, 1.f - t * t));
    float cm = t * cosM - st * sinM;
    S += expf(cm - 1.f) - expf(t - 1.f);     // swap raw target term for margin term
    S = fmaxf(S, 1e-30f);
    g_rowloss[row] = (1.f + logf(S)) - cm;
}

__global__ void k_reduce(float* __restrict__ out, int N) {
    __shared__ float red[8];
    float s = 0.f;
    for (int i = threadIdx.x; i < N; i += blockDim.x) s += g_rowloss[i];
    #pragma unroll
    for (int m = 16; m; m >>= 1) s += __shfl_xor_sync(0xffffffffu, s, m);
    if ((threadIdx.x & 31) == 0) red[threadIdx.x >> 5] = s;
    __syncthreads();
    if (threadIdx.x < 32) {
        float v = (threadIdx.x < (blockDim.x >> 5)) ? red[threadIdx.x] : 0.f;
        #pragma unroll
        for (int m = 16; m; m >>= 1) v += __shfl_xor_sync(0xffffffffu, v, m);
        if (threadIdx.x == 0) out[0] = v / (float)N;
    }
}

extern "C" void kernel_launch(void* const* d_in, const int* in_sizes, int n_in,
                              void* d_out, int out_size) {
    const float* x   = (const float*)d_in[0];
    const int*   lab = (const int*)d_in[1];
    const float* w   = (const float*)d_in[2];
    int N = in_sizes[0] / EDIM;
    int C = in_sizes[2] / EDIM;
    int ncb = (C + 255) >> 8;

    cudaFuncSetAttribute(k_lse_mma, cudaFuncAttributeMaxDynamicSharedMemorySize, SM_TOT);

    k_norm_rows<<<(N + 3) / 4, 128>>>(x, N, 0);
    k_norm_rows<<<(C + 3) / 4, 128>>>(w, C, 1);
    k_prep_labels<<<1, 256>>>(lab, N);
    k_lse_mma<<<NPERS, 256, SM_TOT>>>(N, C);       // position 4 -> lands in ncu's profiled slot
    k_target_dot<<<N, 128>>>();

    float cM = (float)cos(4.0);   // MARGIN = 4 rad
    float sM = (float)sin(4.0);
    k_combine<<<(N + 255) / 256, 256>>>(N, ncb, cM, sM);
    k_reduce<<<1, 256>>>((float*)d_out, N);
}